// round 16
// baseline (speedup 1.0000x reference)
#include <cuda_runtime.h>
#include <cuda_bf16.h>
#include <math.h>
#include <stdint.h>

#define TOKENS 2048
#define DIN    1024
#define DQ     256
#define NH     8
#define NQ     2048   // NH*DQ
#define NSQ    256
#define DQH    128
#define TK     10
#define NR     16384  // TOKENS*NH
#define NEG_INF (-3.0e38f)

#define SPLIT_SZ ((size_t)2048 * 1024)
#define KSPLIT   (NSQ * DQH)          // 32768

// ---------------- scratch (device globals; no allocations allowed) ----------
__device__ __nv_bfloat16 g_qs[2 * SPLIT_SZ * 2];        // 16 MB q splits hi/lo [2048][2048]
__device__ __nv_bfloat16 g_xs[2 * SPLIT_SZ];            // 8 MB  x splits [m][k] hi,lo
__device__ __nv_bfloat16 g_ws[2 * SPLIT_SZ];            // 8 MB  Wq^T splits [n][k] hi,lo
__device__ __nv_bfloat16 g_k1s[2 * KSPLIT];             // K1 splits [n][k] hi,lo
__device__ __nv_bfloat16 g_k2s[2 * KSPLIT];
__device__ float g_s[(size_t)NR * 512];                 // 32 MB scores [row][s1|s2]
__device__ int   g_eidx[NR * TK];
__device__ float g_ew[NR * TK];

__device__ __forceinline__ uint32_t smem_u32(const void* p) {
    uint32_t a;
    asm("{ .reg .u64 t; cvta.to.shared.u64 t, %1; cvt.u32.u64 %0, t; }" : "=r"(a) : "l"(p));
    return a;
}
__device__ __forceinline__ void ldsm4(uint32_t* r, uint32_t addr) {
    asm volatile("ldmatrix.sync.aligned.m8n8.x4.shared.b16 {%0,%1,%2,%3}, [%4];"
                 : "=r"(r[0]), "=r"(r[1]), "=r"(r[2]), "=r"(r[3]) : "r"(addr));
}
__device__ __forceinline__ void mma16816(float* c, const uint32_t* a, const uint32_t* b) {
    asm volatile("mma.sync.aligned.m16n8k16.row.col.f32.bf16.bf16.f32 "
                 "{%0,%1,%2,%3}, {%4,%5,%6,%7}, {%8,%9}, {%0,%1,%2,%3};"
                 : "+f"(c[0]), "+f"(c[1]), "+f"(c[2]), "+f"(c[3])
                 : "r"(a[0]), "r"(a[1]), "r"(a[2]), "r"(a[3]), "r"(b[0]), "r"(b[1]));
}
// order-preserving float->uint encoding (monotone: a<b <=> enc(a)<enc(b))
__device__ __forceinline__ uint32_t fenc(float f) {
    uint32_t b = __float_as_uint(f);
    return (b & 0x80000000u) ? ~b : (b | 0x80000000u);
}
__device__ __forceinline__ float fdec(uint32_t u) {
    uint32_t b = (u & 0x80000000u) ? (u & 0x7FFFFFFFu) : ~u;
    return __uint_as_float(b);
}

// ---------------- Kernel P: fused prep (split_x | split_wq | ksplit) ---------
__global__ __launch_bounds__(256) void prep_kernel(const float* __restrict__ x,
                                                   const float* __restrict__ Wq,
                                                   const float* __restrict__ K1,
                                                   const float* __restrict__ K2) {
    __shared__ float t[32][33];
    int b = blockIdx.x;
    if (b < 2048) {
        size_t i = ((size_t)b * 256 + threadIdx.x) * 4;
        float4 v = *(const float4*)(x + i);
        float vv[4] = {v.x, v.y, v.z, v.w};
        __nv_bfloat16 b0[4], b1[4];
#pragma unroll
        for (int c = 0; c < 4; c++) {
            b0[c] = __float2bfloat16(vv[c]);
            b1[c] = __float2bfloat16(vv[c] - __bfloat162float(b0[c]));
        }
#pragma unroll
        for (int c = 0; c < 4; c += 2) {
            *(__nv_bfloat162*)(g_xs + i + c)            = __nv_bfloat162(b0[c], b0[c + 1]);
            *(__nv_bfloat162*)(g_xs + SPLIT_SZ + i + c) = __nv_bfloat162(b1[c], b1[c + 1]);
        }
    } else if (b < 4096) {
        int bb = b - 2048;
        int n0 = (bb & 63) * 32, k0 = (bb >> 6) * 32;
        int tx = threadIdx.x & 31, ty = threadIdx.x >> 5;
#pragma unroll
        for (int j = 0; j < 4; j++)
            t[ty + j * 8][tx] = Wq[(size_t)(k0 + ty + j * 8) * NQ + n0 + tx];
        __syncthreads();
#pragma unroll
        for (int j = 0; j < 4; j++) {
            int nl = ty + j * 8;
            float v = t[tx][nl];
            __nv_bfloat16 b0 = __float2bfloat16(v);
            __nv_bfloat16 b1 = __float2bfloat16(v - __bfloat162float(b0));
            size_t o = (size_t)(n0 + nl) * DIN + k0 + tx;
            g_ws[o] = b0; g_ws[SPLIT_SZ + o] = b1;
        }
    } else {
        int i = (b - 4096) * 256 + threadIdx.x;
        float v1 = K1[i], v2 = K2[i];
        __nv_bfloat16 h1 = __float2bfloat16(v1);
        __nv_bfloat16 h2 = __float2bfloat16(v2);
        g_k1s[i] = h1; g_k1s[KSPLIT + i] = __float2bfloat16(v1 - __bfloat162float(h1));
        g_k2s[i] = h2; g_k2s[KSPLIT + i] = __float2bfloat16(v2 - __bfloat162float(h2));
    }
}

// ---------------- Kernel 1: mma.sync GEMM q = x @ Wq + bq (bf16x2, 3 prod) --
#define KCHUNK   32
#define NCHUNKS  32
#define ROWB     80
#define PLANE_B  (128 * ROWB)      // 10240
#define STAGE_B  (4 * PLANE_B)     // 40960
#define GEMM_SMEM (2 * STAGE_B)    // 81920

__global__ __launch_bounds__(256) void gemm_tc_kernel(const float* __restrict__ bias, int moff) {
    extern __shared__ char smem[];
    uint32_t sb = smem_u32(smem);
    int tid = threadIdx.x, lane = tid & 31, warp = tid >> 5;
    int warpM = warp >> 2, warpN = warp & 3;
    int bm = blockIdx.y * 128 + moff, bn = blockIdx.x * 128;

    float acc[4][4][4];
#pragma unroll
    for (int i = 0; i < 4; i++)
#pragma unroll
        for (int j = 0; j < 4; j++)
#pragma unroll
            for (int k = 0; k < 4; k++) acc[i][j][k] = 0.f;

    auto issue_chunk = [&](int c) {
        int k0 = c * KCHUNK;
        uint32_t stage = sb + (c & 1) * STAGE_B;
#pragma unroll
        for (int i = 0; i < 8; i++) {
            int idx = tid + i * 256;
            int p = idx >> 9, r = (idx >> 2) & 127, s = idx & 3;
            const __nv_bfloat16* src = (p < 2)
                ? (g_xs + (size_t)p * SPLIT_SZ + (size_t)(bm + r) * DIN + k0 + s * 8)
                : (g_ws + (size_t)(p - 2) * SPLIT_SZ + (size_t)(bn + r) * DIN + k0 + s * 8);
            uint32_t sa = stage + p * PLANE_B + r * ROWB + s * 16;
            asm volatile("cp.async.cg.shared.global [%0], [%1], 16;" :: "r"(sa), "l"(src));
        }
        asm volatile("cp.async.commit_group;" ::: "memory");
    };

    issue_chunk(0);

    int g = lane >> 3, rr = lane & 7;
    for (int c = 0; c < NCHUNKS; c++) {
        if (c + 1 < NCHUNKS) {
            issue_chunk(c + 1);
            asm volatile("cp.async.wait_group 1;" ::: "memory");
        } else {
            asm volatile("cp.async.wait_group 0;" ::: "memory");
        }
        __syncthreads();
        uint32_t stage = sb + (c & 1) * STAGE_B;

#pragma unroll
        for (int k16 = 0; k16 < 2; k16++) {
            uint32_t ah[4][4], al[4][4], bh[4][2], bl[4][2];
#pragma unroll
            for (int mt = 0; mt < 4; mt++) {
                uint32_t rowA = warpM * 64 + mt * 16 + (g & 1) * 8 + rr;
                uint32_t seg  = k16 * 2 + (g >> 1);
                ldsm4(ah[mt], stage + 0 * PLANE_B + rowA * ROWB + seg * 16);
                ldsm4(al[mt], stage + 1 * PLANE_B + rowA * ROWB + seg * 16);
            }
#pragma unroll
            for (int nb = 0; nb < 2; nb++) {
                uint32_t rowB = warpN * 32 + nb * 16 + (g >> 1) * 8 + rr;
                uint32_t seg  = k16 * 2 + (g & 1);
                uint32_t t0[4], t1[4];
                ldsm4(t0, stage + 2 * PLANE_B + rowB * ROWB + seg * 16);
                ldsm4(t1, stage + 3 * PLANE_B + rowB * ROWB + seg * 16);
                bh[nb * 2][0] = t0[0]; bh[nb * 2][1] = t0[1];
                bh[nb * 2 + 1][0] = t0[2]; bh[nb * 2 + 1][1] = t0[3];
                bl[nb * 2][0] = t1[0]; bl[nb * 2][1] = t1[1];
                bl[nb * 2 + 1][0] = t1[2]; bl[nb * 2 + 1][1] = t1[3];
            }
#pragma unroll
            for (int mt = 0; mt < 4; mt++)
#pragma unroll
                for (int nt = 0; nt < 4; nt++) mma16816(acc[mt][nt], ah[mt], bh[nt]);
#pragma unroll
            for (int mt = 0; mt < 4; mt++)
#pragma unroll
                for (int nt = 0; nt < 4; nt++) mma16816(acc[mt][nt], ah[mt], bl[nt]);
#pragma unroll
            for (int mt = 0; mt < 4; mt++)
#pragma unroll
                for (int nt = 0; nt < 4; nt++) mma16816(acc[mt][nt], al[mt], bh[nt]);
        }
        __syncthreads();
    }

    // epilogue: bias add, then write q as bf16 hi/lo split pairs
#pragma unroll
    for (int mt = 0; mt < 4; mt++) {
        int row = bm + warpM * 64 + mt * 16 + (lane >> 2);
#pragma unroll
        for (int nt = 0; nt < 4; nt++) {
            int col = bn + warpN * 32 + nt * 8 + 2 * (lane & 3);
            float b0 = bias[col], b1 = bias[col + 1];
#pragma unroll
            for (int h = 0; h < 2; h++) {
                float v0 = acc[mt][nt][h * 2 + 0] + b0;
                float v1 = acc[mt][nt][h * 2 + 1] + b1;
                __nv_bfloat16 h0 = __float2bfloat16(v0);
                __nv_bfloat16 h1 = __float2bfloat16(v1);
                __nv_bfloat16 l0 = __float2bfloat16(v0 - __bfloat162float(h0));
                __nv_bfloat16 l1 = __float2bfloat16(v1 - __bfloat162float(h1));
                size_t o = (size_t)(row + h * 8) * NQ + col;
                *(__nv_bfloat162*)(g_qs + o)                = __nv_bfloat162(h0, h1);
                *(__nv_bfloat162*)(g_qs + 2 * SPLIT_SZ + o) = __nv_bfloat162(l0, l1);
            }
        }
    }
}

// ---------------- Kernel 2: score GEMM (bf16x2, 3 products) ------------------
#define SROWB   272                     // 256B row + 16B skew
#define SA_PL   (128 * SROWB)           // 34816
#define SB_PL   (64 * SROWB)            // 17408
#define SB_OFF  (2 * SA_PL)             // 69632
#define SCORE_SMEM (2 * SA_PL + 2 * SB_PL)  // 104448

__global__ __launch_bounds__(256, 2) void score_kernel(int roff) {
    extern __shared__ char smem[];
    uint32_t sb = smem_u32(smem);
    int tid = threadIdx.x, lane = tid & 31, warp = tid >> 5;
    int warpM = warp >> 2, warpN = warp & 3;
    int half = blockIdx.x;
    int n0 = blockIdx.y * 64;
    int r0 = blockIdx.z * 128 + roff;

#pragma unroll
    for (int i = 0; i < 16; i++) {
        int idx = tid + i * 256;
        int p = idx >> 11, r = (idx >> 4) & 127, s = idx & 15;
        const __nv_bfloat16* src = g_qs + (size_t)p * 2 * SPLIT_SZ
                                 + (size_t)(r0 + r) * DQ + half * DQH + s * 8;
        asm volatile("cp.async.cg.shared.global [%0], [%1], 16;"
                     :: "r"(sb + p * SA_PL + r * SROWB + s * 16), "l"(src));
    }
    const __nv_bfloat16* kbase = half ? g_k2s : g_k1s;
#pragma unroll
    for (int i = 0; i < 8; i++) {
        int idx = tid + i * 256;
        int p = idx >> 10, r = (idx >> 4) & 63, s = idx & 15;
        const __nv_bfloat16* src = kbase + (size_t)p * KSPLIT + (n0 + r) * DQH + s * 8;
        asm volatile("cp.async.cg.shared.global [%0], [%1], 16;"
                     :: "r"(sb + SB_OFF + p * SB_PL + r * SROWB + s * 16), "l"(src));
    }
    asm volatile("cp.async.commit_group;" ::: "memory");
    asm volatile("cp.async.wait_group 0;" ::: "memory");
    __syncthreads();

    float acc[4][2][4];
#pragma unroll
    for (int i = 0; i < 4; i++)
#pragma unroll
        for (int j = 0; j < 2; j++)
#pragma unroll
            for (int k = 0; k < 4; k++) acc[i][j][k] = 0.f;

    int g = lane >> 3, rr = lane & 7;
#pragma unroll 1
    for (int k16 = 0; k16 < 8; k16++) {
        uint32_t ah[4][4], al[4][4], bh[2][2], bl[2][2];
#pragma unroll
        for (int mt = 0; mt < 4; mt++) {
            uint32_t rowA = warpM * 64 + mt * 16 + (g & 1) * 8 + rr;
            uint32_t seg  = k16 * 2 + (g >> 1);
            ldsm4(ah[mt], sb + 0 * SA_PL + rowA * SROWB + seg * 16);
            ldsm4(al[mt], sb + 1 * SA_PL + rowA * SROWB + seg * 16);
        }
        {
            uint32_t rowB = warpN * 16 + (g >> 1) * 8 + rr;
            uint32_t seg  = k16 * 2 + (g & 1);
            uint32_t t0[4], t1[4];
            ldsm4(t0, sb + SB_OFF + 0 * SB_PL + rowB * SROWB + seg * 16);
            ldsm4(t1, sb + SB_OFF + 1 * SB_PL + rowB * SROWB + seg * 16);
            bh[0][0] = t0[0]; bh[0][1] = t0[1]; bh[1][0] = t0[2]; bh[1][1] = t0[3];
            bl[0][0] = t1[0]; bl[0][1] = t1[1]; bl[1][0] = t1[2]; bl[1][1] = t1[3];
        }
        // 3 products (hh, hl, lh); ll term ~2^-18 relative, dropped
#pragma unroll
        for (int mt = 0; mt < 4; mt++)
#pragma unroll
            for (int nt = 0; nt < 2; nt++) mma16816(acc[mt][nt], ah[mt], bh[nt]);
#pragma unroll
        for (int mt = 0; mt < 4; mt++)
#pragma unroll
            for (int nt = 0; nt < 2; nt++) mma16816(acc[mt][nt], ah[mt], bl[nt]);
#pragma unroll
        for (int mt = 0; mt < 4; mt++)
#pragma unroll
            for (int nt = 0; nt < 2; nt++) mma16816(acc[mt][nt], al[mt], bh[nt]);
    }

#pragma unroll
    for (int mt = 0; mt < 4; mt++) {
        int row = r0 + warpM * 64 + mt * 16 + (lane >> 2);
#pragma unroll
        for (int nt = 0; nt < 2; nt++) {
            int col = half * 256 + n0 + warpN * 16 + nt * 8 + 2 * (lane & 3);
            *(float2*)(g_s + (size_t)row * 512 + col) =
                make_float2(acc[mt][nt][0], acc[mt][nt][1]);
            *(float2*)(g_s + (size_t)(row + 8) * 512 + col) =
                make_float2(acc[mt][nt][2], acc[mt][nt][3]);
        }
    }
}

// ---------------- Kernel 3: topk + softmax (half-warp dual extraction) -------
__global__ __launch_bounds__(512) void topk_kernel(int roff) {
    __shared__ __align__(16) float ss[16][512];
    int tid = threadIdx.x;
    int lane = tid & 31;
    int warp = tid >> 5;       // 0..15, one row each
    int r0 = blockIdx.x * 16 + roff;
    const uint32_t FULL = 0xFFFFFFFFu;

#pragma unroll
    for (int i = 0; i < 4; i++) {
        int idx = tid + i * 512;
        int row = idx >> 7, c4 = idx & 127;
        ((float4*)ss[row])[c4] = ((const float4*)(g_s + (size_t)(r0 + row) * 512))[c4];
    }
    __syncthreads();

    int rr = warp;
    int r = r0 + rr;
    int half = lane >> 4;          // 0: s1, 1: s2
    int sl   = lane & 15;          // sub-lane
    uint32_t hmask = half ? 0xFFFF0000u : 0x0000FFFFu;

    // ---- dual extraction: 16 values per lane, both lists in 10 iterations ---
    {
        const float* src = ss[rr] + half * 256;
        float v[16];
#pragma unroll
        for (int q = 0; q < 4; q++) {
            float4 f4 = ((const float4*)src)[sl * 4 + q];
            v[q * 4 + 0] = f4.x; v[q * 4 + 1] = f4.y;
            v[q * 4 + 2] = f4.z; v[q * 4 + 3] = f4.w;
        }
        float lmax = v[0]; int lj = 0;
#pragma unroll
        for (int j = 1; j < 16; j++)
            if (v[j] > lmax) { lmax = v[j]; lj = j; }
#pragma unroll 1
        for (int t = 0; t < TK; t++) {
            uint32_t u = fenc(lmax);
            uint32_t gm = u;
#pragma unroll
            for (int off = 8; off; off >>= 1) {
                uint32_t o = __shfl_xor_sync(FULL, gm, off);
                gm = o > gm ? o : gm;
            }
            uint32_t mask = __ballot_sync(FULL, u == gm) & hmask;
            int wl = __ffs(mask) - 1;
            if (lane == wl) {
                ss[rr][half * 20 + t] = lmax;
                ss[rr][half * 20 + 10 + t] = __int_as_float(sl * 16 + lj);
                v[lj] = NEG_INF;
                lmax = v[0]; lj = 0;
#pragma unroll
                for (int j = 1; j < 16; j++)
                    if (v[j] > lmax) { lmax = v[j]; lj = j; }
            }
        }
        __syncwarp();
    }

    // ---- combine 10x10 -> top-10; positions p = lane*4+t (lexicographic) ----
    float cv[4];
#pragma unroll
    for (int t = 0; t < 4; t++) {
        int p = lane * 4 + t;
        if (p < 100) {
            int i = p / 10, j = p - i * 10;
            cv[t] = ss[rr][i] + ss[rr][20 + j];
        } else cv[t] = NEG_INF;
    }
    float clmax = cv[0]; int ct = 0;
#pragma unroll
    for (int t = 1; t < 4; t++)
        if (cv[t] > clmax) { clmax = cv[t]; ct = t; }

    float m = 0.f, sum = 0.f, myval = 0.f;
    int myidx = 0;
#pragma unroll 1
    for (int t = 0; t < TK; t++) {
        uint32_t u = fenc(clmax);
        uint32_t gm = u;
#pragma unroll
        for (int off = 16; off; off >>= 1) {
            uint32_t o = __shfl_xor_sync(FULL, gm, off);
            gm = o > gm ? o : gm;
        }
        uint32_t mask = __ballot_sync(FULL, u == gm);
        int wl = __ffs(mask) - 1;
        float mv = fdec(gm);
        if (t == 0) m = mv;
        sum += __expf(mv - m);
        int wslot = __shfl_sync(FULL, ct, wl);
        int p = wl * 4 + wslot;
        if (lane == t) {
            myval = mv;
            int i = p / 10, j = p - i * 10;
            myidx = __float_as_int(ss[rr][10 + i]) * NSQ + __float_as_int(ss[rr][30 + j]);
        }
        if (lane == wl) {
            cv[ct] = NEG_INF;
            clmax = cv[0]; ct = 0;
#pragma unroll
            for (int uu = 1; uu < 4; uu++)
                if (cv[uu] > clmax) { clmax = cv[uu]; ct = uu; }
        }
    }
    if (lane < TK) {
        g_eidx[r * TK + lane] = myidx;
        g_ew[r * TK + lane]   = __expf(myval - m) / sum;
    }
}

// ---------------- Kernel 4: expert gather + GELU + weighted combine ---------
__global__ __launch_bounds__(256, 4) void expert_kernel(const float* __restrict__ x,
                                                        const float* __restrict__ W_up,
                                                        const float* __restrict__ W_down,
                                                        float* __restrict__ out, int toff) {
    __shared__ __align__(16) float xs[DIN];
    __shared__ float hs[80];
    __shared__ int   es[80];
    int token = blockIdx.x + toff;
    int tid = threadIdx.x;

    ((float4*)xs)[tid] = ((const float4*)(x + (size_t)token * DIN))[tid];
    if (tid < 80) es[tid] = g_eidx[token * 80 + tid];
    __syncthreads();

    int warp = tid >> 5, lane = tid & 31;
    {
        const float4* wrow[TK];
#pragma unroll
        for (int k = 0; k < TK; k++)
            wrow[k] = (const float4*)(W_down + (size_t)es[warp * TK + k] * DIN);
        float acc[TK];
#pragma unroll
        for (int k = 0; k < TK; k++) acc[k] = 0.f;
        const float4* x4 = (const float4*)xs;
#pragma unroll
        for (int i = 0; i < 8; i++) {
            float4 v4 = x4[lane + i * 32];
#pragma unroll
            for (int k = 0; k < TK; k++) {
                float4 w4 = wrow[k][lane + i * 32];
                acc[k] += w4.x * v4.x + w4.y * v4.y + w4.z * v4.z + w4.w * v4.w;
            }
        }
#pragma unroll
        for (int k = 0; k < TK; k++) {
            float a = acc[k];
#pragma unroll
            for (int off = 16; off; off >>= 1) a += __shfl_xor_sync(0xFFFFFFFFu, a, off);
            if (lane == k) {
                float g = 0.5f * a * (1.0f + erff(a * 0.70710678118654752f));
                hs[warp * TK + k] = g * g_ew[token * 80 + warp * TK + k];
            }
        }
    }
    __syncthreads();

    float4 acc4 = make_float4(0.f, 0.f, 0.f, 0.f);
#pragma unroll 10
    for (int e = 0; e < 80; e++) {
        float h = hs[e];
        float4 u4 = ((const float4*)(W_up + (size_t)es[e] * DIN))[tid];
        acc4.x += h * u4.x; acc4.y += h * u4.y;
        acc4.z += h * u4.z; acc4.w += h * u4.w;
    }
    ((float4*)(out + (size_t)token * DIN))[tid] = acc4;
}

// ---------------- launch: two-stream token-half pipeline ---------------------
extern "C" void kernel_launch(void* const* d_in, const int* in_sizes, int n_in,
                              void* d_out, int out_size) {
    const float* x      = (const float*)d_in[0];
    const float* Wq     = (const float*)d_in[1];
    const float* bq     = (const float*)d_in[2];
    const float* K1     = (const float*)d_in[3];
    const float* K2     = (const float*)d_in[4];
    const float* W_up   = (const float*)d_in[5];
    const float* W_down = (const float*)d_in[6];
    float* out = (float*)d_out;

    cudaFuncSetAttribute(gemm_tc_kernel, cudaFuncAttributeMaxDynamicSharedMemorySize, GEMM_SMEM);
    cudaFuncSetAttribute(score_kernel, cudaFuncAttributeMaxDynamicSharedMemorySize, SCORE_SMEM);

    // Created fresh each call; never destroyed (destroying a forked stream
    // mid-capture invalidates the graph; kernel_launch host code runs only a
    // handful of times, so this leaks ~3 streams total, no device memory).
    cudaStream_t s2;
    cudaStreamCreateWithFlags(&s2, cudaStreamNonBlocking);
    cudaEvent_t e0, e1;
    cudaEventCreateWithFlags(&e0, cudaEventDisableTiming);
    cudaEventCreateWithFlags(&e1, cudaEventDisableTiming);

    prep_kernel<<<4224, 256>>>(x, Wq, K1, K2);
    cudaEventRecord(e0, 0);
    cudaStreamWaitEvent(s2, e0, 0);

    // half 0 (tokens 0-1023) on default stream; half 1 on s2
    gemm_tc_kernel<<<dim3(16, 8), 256, GEMM_SMEM, 0>>>(bq, 0);
    gemm_tc_kernel<<<dim3(16, 8), 256, GEMM_SMEM, s2>>>(bq, 1024);
    score_kernel<<<dim3(2, 4, 64), 256, SCORE_SMEM, 0>>>(0);
    score_kernel<<<dim3(2, 4, 64), 256, SCORE_SMEM, s2>>>(8192);
    topk_kernel<<<512, 512, 0, 0>>>(0);
    topk_kernel<<<512, 512, 0, s2>>>(8192);
    expert_kernel<<<1024, 256, 0, 0>>>(x, W_up, W_down, out, 0);
    expert_kernel<<<1024, 256, 0, s2>>>(x, W_up, W_down, out, 1024);

    cudaEventRecord(e1, s2);
    cudaStreamWaitEvent(0, e1, 0);
}

// round 17
// speedup vs baseline: 1.2271x; 1.2271x over previous
#include <cuda_runtime.h>
#include <cuda_bf16.h>
#include <math.h>
#include <stdint.h>

#define TOKENS 2048
#define DIN    1024
#define DQ     256
#define NH     8
#define NQ     2048   // NH*DQ
#define NSQ    256
#define DQH    128
#define TK     10
#define NR     16384  // TOKENS*NH
#define NEG_INF (-3.0e38f)

#define SPLIT_SZ ((size_t)2048 * 1024)
#define KSPLIT   (NSQ * DQH)          // 32768

// ---------------- scratch (device globals; no allocations allowed) ----------
__device__ __nv_bfloat16 g_qs[2 * SPLIT_SZ * 2];        // 16 MB q splits hi/lo [2048][2048]
__device__ __nv_bfloat16 g_xs[2 * SPLIT_SZ];            // 8 MB  x splits [m][k] hi,lo
__device__ __nv_bfloat16 g_ws[2 * SPLIT_SZ];            // 8 MB  Wq^T splits [n][k] hi,lo
__device__ __nv_bfloat16 g_k1s[2 * KSPLIT];             // K1 splits [n][k] hi,lo
__device__ __nv_bfloat16 g_k2s[2 * KSPLIT];
__device__ float g_s[(size_t)NR * 512];                 // 32 MB scores [row][s1|s2]

__device__ __forceinline__ uint32_t smem_u32(const void* p) {
    uint32_t a;
    asm("{ .reg .u64 t; cvta.to.shared.u64 t, %1; cvt.u32.u64 %0, t; }" : "=r"(a) : "l"(p));
    return a;
}
__device__ __forceinline__ void ldsm4(uint32_t* r, uint32_t addr) {
    asm volatile("ldmatrix.sync.aligned.m8n8.x4.shared.b16 {%0,%1,%2,%3}, [%4];"
                 : "=r"(r[0]), "=r"(r[1]), "=r"(r[2]), "=r"(r[3]) : "r"(addr));
}
__device__ __forceinline__ void mma16816(float* c, const uint32_t* a, const uint32_t* b) {
    asm volatile("mma.sync.aligned.m16n8k16.row.col.f32.bf16.bf16.f32 "
                 "{%0,%1,%2,%3}, {%4,%5,%6,%7}, {%8,%9}, {%0,%1,%2,%3};"
                 : "+f"(c[0]), "+f"(c[1]), "+f"(c[2]), "+f"(c[3])
                 : "r"(a[0]), "r"(a[1]), "r"(a[2]), "r"(a[3]), "r"(b[0]), "r"(b[1]));
}
// order-preserving float->uint encoding (monotone: a<b <=> enc(a)<enc(b))
__device__ __forceinline__ uint32_t fenc(float f) {
    uint32_t b = __float_as_uint(f);
    return (b & 0x80000000u) ? ~b : (b | 0x80000000u);
}
__device__ __forceinline__ float fdec(uint32_t u) {
    uint32_t b = (u & 0x80000000u) ? (u & 0x7FFFFFFFu) : ~u;
    return __uint_as_float(b);
}

// ---------------- Kernel P: fused prep (split_x | split_wq | ksplit) ---------
__global__ __launch_bounds__(256) void prep_kernel(const float* __restrict__ x,
                                                   const float* __restrict__ Wq,
                                                   const float* __restrict__ K1,
                                                   const float* __restrict__ K2) {
    __shared__ float t[32][33];
    int b = blockIdx.x;
    if (b < 2048) {
        size_t i = ((size_t)b * 256 + threadIdx.x) * 4;
        float4 v = *(const float4*)(x + i);
        float vv[4] = {v.x, v.y, v.z, v.w};
        __nv_bfloat16 b0[4], b1[4];
#pragma unroll
        for (int c = 0; c < 4; c++) {
            b0[c] = __float2bfloat16(vv[c]);
            b1[c] = __float2bfloat16(vv[c] - __bfloat162float(b0[c]));
        }
#pragma unroll
        for (int c = 0; c < 4; c += 2) {
            *(__nv_bfloat162*)(g_xs + i + c)            = __nv_bfloat162(b0[c], b0[c + 1]);
            *(__nv_bfloat162*)(g_xs + SPLIT_SZ + i + c) = __nv_bfloat162(b1[c], b1[c + 1]);
        }
    } else if (b < 4096) {
        int bb = b - 2048;
        int n0 = (bb & 63) * 32, k0 = (bb >> 6) * 32;
        int tx = threadIdx.x & 31, ty = threadIdx.x >> 5;
#pragma unroll
        for (int j = 0; j < 4; j++)
            t[ty + j * 8][tx] = Wq[(size_t)(k0 + ty + j * 8) * NQ + n0 + tx];
        __syncthreads();
#pragma unroll
        for (int j = 0; j < 4; j++) {
            int nl = ty + j * 8;
            float v = t[tx][nl];
            __nv_bfloat16 b0 = __float2bfloat16(v);
            __nv_bfloat16 b1 = __float2bfloat16(v - __bfloat162float(b0));
            size_t o = (size_t)(n0 + nl) * DIN + k0 + tx;
            g_ws[o] = b0; g_ws[SPLIT_SZ + o] = b1;
        }
    } else {
        int i = (b - 4096) * 256 + threadIdx.x;
        float v1 = K1[i], v2 = K2[i];
        __nv_bfloat16 h1 = __float2bfloat16(v1);
        __nv_bfloat16 h2 = __float2bfloat16(v2);
        g_k1s[i] = h1; g_k1s[KSPLIT + i] = __float2bfloat16(v1 - __bfloat162float(h1));
        g_k2s[i] = h2; g_k2s[KSPLIT + i] = __float2bfloat16(v2 - __bfloat162float(h2));
    }
}

// ---------------- Kernel 1: mma.sync GEMM q = x @ Wq + bq (bf16x2, 3 prod) --
#define KCHUNK   32
#define NCHUNKS  32
#define ROWB     80
#define PLANE_B  (128 * ROWB)      // 10240
#define STAGE_B  (4 * PLANE_B)     // 40960
#define GEMM_SMEM (2 * STAGE_B)    // 81920

__global__ __launch_bounds__(256) void gemm_tc_kernel(const float* __restrict__ bias) {
    extern __shared__ char smem[];
    uint32_t sb = smem_u32(smem);
    int tid = threadIdx.x, lane = tid & 31, warp = tid >> 5;
    int warpM = warp >> 2, warpN = warp & 3;
    int bm = blockIdx.y * 128, bn = blockIdx.x * 128;

    float acc[4][4][4];
#pragma unroll
    for (int i = 0; i < 4; i++)
#pragma unroll
        for (int j = 0; j < 4; j++)
#pragma unroll
            for (int k = 0; k < 4; k++) acc[i][j][k] = 0.f;

    auto issue_chunk = [&](int c) {
        int k0 = c * KCHUNK;
        uint32_t stage = sb + (c & 1) * STAGE_B;
#pragma unroll
        for (int i = 0; i < 8; i++) {
            int idx = tid + i * 256;
            int p = idx >> 9, r = (idx >> 2) & 127, s = idx & 3;
            const __nv_bfloat16* src = (p < 2)
                ? (g_xs + (size_t)p * SPLIT_SZ + (size_t)(bm + r) * DIN + k0 + s * 8)
                : (g_ws + (size_t)(p - 2) * SPLIT_SZ + (size_t)(bn + r) * DIN + k0 + s * 8);
            uint32_t sa = stage + p * PLANE_B + r * ROWB + s * 16;
            asm volatile("cp.async.cg.shared.global [%0], [%1], 16;" :: "r"(sa), "l"(src));
        }
        asm volatile("cp.async.commit_group;" ::: "memory");
    };

    issue_chunk(0);

    int g = lane >> 3, rr = lane & 7;
    for (int c = 0; c < NCHUNKS; c++) {
        if (c + 1 < NCHUNKS) {
            issue_chunk(c + 1);
            asm volatile("cp.async.wait_group 1;" ::: "memory");
        } else {
            asm volatile("cp.async.wait_group 0;" ::: "memory");
        }
        __syncthreads();
        uint32_t stage = sb + (c & 1) * STAGE_B;

#pragma unroll
        for (int k16 = 0; k16 < 2; k16++) {
            uint32_t ah[4][4], al[4][4], bh[4][2], bl[4][2];
#pragma unroll
            for (int mt = 0; mt < 4; mt++) {
                uint32_t rowA = warpM * 64 + mt * 16 + (g & 1) * 8 + rr;
                uint32_t seg  = k16 * 2 + (g >> 1);
                ldsm4(ah[mt], stage + 0 * PLANE_B + rowA * ROWB + seg * 16);
                ldsm4(al[mt], stage + 1 * PLANE_B + rowA * ROWB + seg * 16);
            }
#pragma unroll
            for (int nb = 0; nb < 2; nb++) {
                uint32_t rowB = warpN * 32 + nb * 16 + (g >> 1) * 8 + rr;
                uint32_t seg  = k16 * 2 + (g & 1);
                uint32_t t0[4], t1[4];
                ldsm4(t0, stage + 2 * PLANE_B + rowB * ROWB + seg * 16);
                ldsm4(t1, stage + 3 * PLANE_B + rowB * ROWB + seg * 16);
                bh[nb * 2][0] = t0[0]; bh[nb * 2][1] = t0[1];
                bh[nb * 2 + 1][0] = t0[2]; bh[nb * 2 + 1][1] = t0[3];
                bl[nb * 2][0] = t1[0]; bl[nb * 2][1] = t1[1];
                bl[nb * 2 + 1][0] = t1[2]; bl[nb * 2 + 1][1] = t1[3];
            }
#pragma unroll
            for (int mt = 0; mt < 4; mt++)
#pragma unroll
                for (int nt = 0; nt < 4; nt++) mma16816(acc[mt][nt], ah[mt], bh[nt]);
#pragma unroll
            for (int mt = 0; mt < 4; mt++)
#pragma unroll
                for (int nt = 0; nt < 4; nt++) mma16816(acc[mt][nt], ah[mt], bl[nt]);
#pragma unroll
            for (int mt = 0; mt < 4; mt++)
#pragma unroll
                for (int nt = 0; nt < 4; nt++) mma16816(acc[mt][nt], al[mt], bh[nt]);
        }
        __syncthreads();
    }

    // epilogue: bias add, then write q as bf16 hi/lo split pairs
#pragma unroll
    for (int mt = 0; mt < 4; mt++) {
        int row = bm + warpM * 64 + mt * 16 + (lane >> 2);
#pragma unroll
        for (int nt = 0; nt < 4; nt++) {
            int col = bn + warpN * 32 + nt * 8 + 2 * (lane & 3);
            float b0 = bias[col], b1 = bias[col + 1];
#pragma unroll
            for (int h = 0; h < 2; h++) {
                float v0 = acc[mt][nt][h * 2 + 0] + b0;
                float v1 = acc[mt][nt][h * 2 + 1] + b1;
                __nv_bfloat16 h0 = __float2bfloat16(v0);
                __nv_bfloat16 h1 = __float2bfloat16(v1);
                __nv_bfloat16 l0 = __float2bfloat16(v0 - __bfloat162float(h0));
                __nv_bfloat16 l1 = __float2bfloat16(v1 - __bfloat162float(h1));
                size_t o = (size_t)(row + h * 8) * NQ + col;
                *(__nv_bfloat162*)(g_qs + o)                = __nv_bfloat162(h0, h1);
                *(__nv_bfloat162*)(g_qs + 2 * SPLIT_SZ + o) = __nv_bfloat162(l0, l1);
            }
        }
    }
}

// ---------------- Kernel 2: score GEMM (bf16x2, 3 products) ------------------
#define SROWB   272                     // 256B row + 16B skew
#define SA_PL   (128 * SROWB)           // 34816
#define SB_PL   (64 * SROWB)            // 17408
#define SB_OFF  (2 * SA_PL)             // 69632
#define SCORE_SMEM (2 * SA_PL + 2 * SB_PL)  // 104448

__global__ __launch_bounds__(256, 2) void score_kernel() {
    extern __shared__ char smem[];
    uint32_t sb = smem_u32(smem);
    int tid = threadIdx.x, lane = tid & 31, warp = tid >> 5;
    int warpM = warp >> 2, warpN = warp & 3;
    int half = blockIdx.x;
    int n0 = blockIdx.y * 64;
    int r0 = blockIdx.z * 128;

#pragma unroll
    for (int i = 0; i < 16; i++) {
        int idx = tid + i * 256;
        int p = idx >> 11, r = (idx >> 4) & 127, s = idx & 15;
        const __nv_bfloat16* src = g_qs + (size_t)p * 2 * SPLIT_SZ
                                 + (size_t)(r0 + r) * DQ + half * DQH + s * 8;
        asm volatile("cp.async.cg.shared.global [%0], [%1], 16;"
                     :: "r"(sb + p * SA_PL + r * SROWB + s * 16), "l"(src));
    }
    const __nv_bfloat16* kbase = half ? g_k2s : g_k1s;
#pragma unroll
    for (int i = 0; i < 8; i++) {
        int idx = tid + i * 256;
        int p = idx >> 10, r = (idx >> 4) & 63, s = idx & 15;
        const __nv_bfloat16* src = kbase + (size_t)p * KSPLIT + (n0 + r) * DQH + s * 8;
        asm volatile("cp.async.cg.shared.global [%0], [%1], 16;"
                     :: "r"(sb + SB_OFF + p * SB_PL + r * SROWB + s * 16), "l"(src));
    }
    asm volatile("cp.async.commit_group;" ::: "memory");
    asm volatile("cp.async.wait_group 0;" ::: "memory");
    __syncthreads();

    float acc[4][2][4];
#pragma unroll
    for (int i = 0; i < 4; i++)
#pragma unroll
        for (int j = 0; j < 2; j++)
#pragma unroll
            for (int k = 0; k < 4; k++) acc[i][j][k] = 0.f;

    int g = lane >> 3, rr = lane & 7;
#pragma unroll 1
    for (int k16 = 0; k16 < 8; k16++) {
        uint32_t ah[4][4], al[4][4], bh[2][2], bl[2][2];
#pragma unroll
        for (int mt = 0; mt < 4; mt++) {
            uint32_t rowA = warpM * 64 + mt * 16 + (g & 1) * 8 + rr;
            uint32_t seg  = k16 * 2 + (g >> 1);
            ldsm4(ah[mt], sb + 0 * SA_PL + rowA * SROWB + seg * 16);
            ldsm4(al[mt], sb + 1 * SA_PL + rowA * SROWB + seg * 16);
        }
        {
            uint32_t rowB = warpN * 16 + (g >> 1) * 8 + rr;
            uint32_t seg  = k16 * 2 + (g & 1);
            uint32_t t0[4], t1[4];
            ldsm4(t0, sb + SB_OFF + 0 * SB_PL + rowB * SROWB + seg * 16);
            ldsm4(t1, sb + SB_OFF + 1 * SB_PL + rowB * SROWB + seg * 16);
            bh[0][0] = t0[0]; bh[0][1] = t0[1]; bh[1][0] = t0[2]; bh[1][1] = t0[3];
            bl[0][0] = t1[0]; bl[0][1] = t1[1]; bl[1][0] = t1[2]; bl[1][1] = t1[3];
        }
        // 3 products (hh, hl, lh); ll term ~2^-18 relative, dropped
#pragma unroll
        for (int mt = 0; mt < 4; mt++)
#pragma unroll
            for (int nt = 0; nt < 2; nt++) mma16816(acc[mt][nt], ah[mt], bh[nt]);
#pragma unroll
        for (int mt = 0; mt < 4; mt++)
#pragma unroll
            for (int nt = 0; nt < 2; nt++) mma16816(acc[mt][nt], ah[mt], bl[nt]);
#pragma unroll
        for (int mt = 0; mt < 4; mt++)
#pragma unroll
            for (int nt = 0; nt < 2; nt++) mma16816(acc[mt][nt], al[mt], bh[nt]);
    }

#pragma unroll
    for (int mt = 0; mt < 4; mt++) {
        int row = r0 + warpM * 64 + mt * 16 + (lane >> 2);
#pragma unroll
        for (int nt = 0; nt < 2; nt++) {
            int col = half * 256 + n0 + warpN * 16 + nt * 8 + 2 * (lane & 3);
            *(float2*)(g_s + (size_t)row * 512 + col) =
                make_float2(acc[mt][nt][0], acc[mt][nt][1]);
            *(float2*)(g_s + (size_t)(row + 8) * 512 + col) =
                make_float2(acc[mt][nt][2], acc[mt][nt][3]);
        }
    }
}

// ---------------- Kernel 3: FUSED topk + expert gather/GELU/combine ----------
// Block = token. 8 warps; warp w does topk for (token,head=w), then gathers.
// Topk ALU work hides under co-resident CTAs' DRAM gathers.
__global__ __launch_bounds__(256, 4) void expert_kernel(const float* __restrict__ x,
                                                        const float* __restrict__ W_up,
                                                        const float* __restrict__ W_down,
                                                        float* __restrict__ out) {
    __shared__ __align__(16) float ss[8][512];   // 16 KB scores
    __shared__ __align__(16) float xs[DIN];      // 4 KB
    __shared__ float hs[80];
    __shared__ float wsm[80];
    __shared__ int   es[80];
    int token = blockIdx.x;
    int tid = threadIdx.x;
    int warp = tid >> 5, lane = tid & 31;
    const uint32_t FULL = 0xFFFFFFFFu;

    ((float4*)xs)[tid] = ((const float4*)(x + (size_t)token * DIN))[tid];
    // load 8 score rows (token*8 .. token*8+7): 1024 float4
#pragma unroll
    for (int i = 0; i < 4; i++) {
        int idx = tid + i * 256;
        int row = idx >> 7, c4 = idx & 127;
        ((float4*)ss[row])[c4] =
            ((const float4*)(g_s + (size_t)(token * 8 + row) * 512))[c4];
    }
    __syncthreads();

    // ---- per-warp topk on row rr = warp ----
    {
        int rr = warp;
        int half = lane >> 4;
        int sl   = lane & 15;
        uint32_t hmask = half ? 0xFFFF0000u : 0x0000FFFFu;
        {
            const float* src = ss[rr] + half * 256;
            float v[16];
#pragma unroll
            for (int q = 0; q < 4; q++) {
                float4 f4 = ((const float4*)src)[sl * 4 + q];
                v[q * 4 + 0] = f4.x; v[q * 4 + 1] = f4.y;
                v[q * 4 + 2] = f4.z; v[q * 4 + 3] = f4.w;
            }
            float lmax = v[0]; int lj = 0;
#pragma unroll
            for (int j = 1; j < 16; j++)
                if (v[j] > lmax) { lmax = v[j]; lj = j; }
#pragma unroll 1
            for (int t = 0; t < TK; t++) {
                uint32_t u = fenc(lmax);
                uint32_t gm = u;
#pragma unroll
                for (int off = 8; off; off >>= 1) {
                    uint32_t o = __shfl_xor_sync(FULL, gm, off);
                    gm = o > gm ? o : gm;
                }
                uint32_t mask = __ballot_sync(FULL, u == gm) & hmask;
                int wl = __ffs(mask) - 1;
                if (lane == wl) {
                    ss[rr][half * 20 + t] = lmax;
                    ss[rr][half * 20 + 10 + t] = __int_as_float(sl * 16 + lj);
                    v[lj] = NEG_INF;
                    lmax = v[0]; lj = 0;
#pragma unroll
                    for (int j = 1; j < 16; j++)
                        if (v[j] > lmax) { lmax = v[j]; lj = j; }
                }
            }
            __syncwarp();
        }

        // combine 10x10 -> top-10
        float cv[4];
#pragma unroll
        for (int t = 0; t < 4; t++) {
            int p = lane * 4 + t;
            if (p < 100) {
                int i = p / 10, j = p - i * 10;
                cv[t] = ss[rr][i] + ss[rr][20 + j];
            } else cv[t] = NEG_INF;
        }
        float clmax = cv[0]; int ct = 0;
#pragma unroll
        for (int t = 1; t < 4; t++)
            if (cv[t] > clmax) { clmax = cv[t]; ct = t; }

        float m = 0.f, sum = 0.f, myval = 0.f;
        int myidx = 0;
#pragma unroll 1
        for (int t = 0; t < TK; t++) {
            uint32_t u = fenc(clmax);
            uint32_t gm = u;
#pragma unroll
            for (int off = 16; off; off >>= 1) {
                uint32_t o = __shfl_xor_sync(FULL, gm, off);
                gm = o > gm ? o : gm;
            }
            uint32_t mask = __ballot_sync(FULL, u == gm);
            int wl = __ffs(mask) - 1;
            float mv = fdec(gm);
            if (t == 0) m = mv;
            sum += __expf(mv - m);
            int wslot = __shfl_sync(FULL, ct, wl);
            int p = wl * 4 + wslot;
            if (lane == t) {
                myval = mv;
                int i = p / 10, j = p - i * 10;
                myidx = __float_as_int(ss[rr][10 + i]) * NSQ + __float_as_int(ss[rr][30 + j]);
            }
            if (lane == wl) {
                cv[ct] = NEG_INF;
                clmax = cv[0]; ct = 0;
#pragma unroll
                for (int uu = 1; uu < 4; uu++)
                    if (cv[uu] > clmax) { clmax = cv[uu]; ct = uu; }
            }
        }
        float inv = 1.0f / sum;
        if (lane < TK) {
            es[warp * TK + lane]  = myidx;
            wsm[warp * TK + lane] = __expf(myval - m) * inv;
        }
    }
    __syncthreads();

    // ---- Phase A: h_e = gelu(x . W_down[e]) * weight ----
    {
        const float4* wrow[TK];
#pragma unroll
        for (int k = 0; k < TK; k++)
            wrow[k] = (const float4*)(W_down + (size_t)es[warp * TK + k] * DIN);
        float acc[TK];
#pragma unroll
        for (int k = 0; k < TK; k++) acc[k] = 0.f;
        const float4* x4 = (const float4*)xs;
#pragma unroll
        for (int i = 0; i < 8; i++) {
            float4 v4 = x4[lane + i * 32];
#pragma unroll
            for (int k = 0; k < TK; k++) {
                float4 w4 = wrow[k][lane + i * 32];
                acc[k] += w4.x * v4.x + w4.y * v4.y + w4.z * v4.z + w4.w * v4.w;
            }
        }
#pragma unroll
        for (int k = 0; k < TK; k++) {
            float a = acc[k];
#pragma unroll
            for (int off = 16; off; off >>= 1) a += __shfl_xor_sync(0xFFFFFFFFu, a, off);
            if (lane == k) {
                float g = 0.5f * a * (1.0f + erff(a * 0.70710678118654752f));
                hs[warp * TK + k] = g * wsm[warp * TK + k];
            }
        }
    }
    __syncthreads();

    // ---- Phase B: out[d] = sum_e h_e * W_up[e][d] ----
    float4 acc4 = make_float4(0.f, 0.f, 0.f, 0.f);
#pragma unroll 10
    for (int e = 0; e < 80; e++) {
        float h = hs[e];
        float4 u4 = ((const float4*)(W_up + (size_t)es[e] * DIN))[tid];
        acc4.x += h * u4.x; acc4.y += h * u4.y;
        acc4.z += h * u4.z; acc4.w += h * u4.w;
    }
    ((float4*)(out + (size_t)token * DIN))[tid] = acc4;
}

// ---------------- launch ----------------------------------------------------
extern "C" void kernel_launch(void* const* d_in, const int* in_sizes, int n_in,
                              void* d_out, int out_size) {
    const float* x      = (const float*)d_in[0];
    const float* Wq     = (const float*)d_in[1];
    const float* bq     = (const float*)d_in[2];
    const float* K1     = (const float*)d_in[3];
    const float* K2     = (const float*)d_in[4];
    const float* W_up   = (const float*)d_in[5];
    const float* W_down = (const float*)d_in[6];
    float* out = (float*)d_out;

    cudaFuncSetAttribute(gemm_tc_kernel, cudaFuncAttributeMaxDynamicSharedMemorySize, GEMM_SMEM);
    cudaFuncSetAttribute(score_kernel, cudaFuncAttributeMaxDynamicSharedMemorySize, SCORE_SMEM);

    prep_kernel<<<4224, 256>>>(x, Wq, K1, K2);
    gemm_tc_kernel<<<dim3(NQ / 128, TOKENS / 128), 256, GEMM_SMEM>>>(bq);
    score_kernel<<<dim3(2, 4, NR / 128), 256, SCORE_SMEM>>>();
    expert_kernel<<<TOKENS, 256>>>(x, W_up, W_down, out);
}